// round 3
// baseline (speedup 1.0000x reference)
#include <cuda_runtime.h>

#define IMG_W 512
#define IMG_H 512
#define ROWS  16
#define NTHREADS 128   // 128 threads * 4 cols = 512 = full row width

// Per-row horizontally-sorted triples for this thread's 4 columns.
struct Sorted {
    float lo[4], mi[4], hi[4];
};

__device__ __forceinline__ void sort3(float a, float b, float c,
                                      float& lo, float& mi, float& hi) {
    float t1 = fminf(a, b);
    float t2 = fmaxf(a, b);
    lo = fminf(t1, c);
    hi = fmaxf(t2, c);
    mi = fmaxf(t1, fminf(t2, c));
}
__device__ __forceinline__ float med3(float a, float b, float c) {
    float t1 = fminf(a, b);
    float t2 = fmaxf(a, b);
    return fmaxf(t1, fminf(t2, c));
}
__device__ __forceinline__ float max3(float a, float b, float c) {
    return fmaxf(fmaxf(a, b), c);
}
__device__ __forceinline__ float min3(float a, float b, float c) {
    return fminf(fminf(a, b), c);
}

// Row pointer is already resolved (y-reflection handled by caller).
__device__ __forceinline__ Sorted hsort_row(const float* __restrict__ rowp,
                                            int tid, int lane, int x4) {
    float4 v = __ldg(reinterpret_cast<const float4*>(rowp) + tid);

    float l = __shfl_up_sync(0xffffffffu, v.w, 1);
    float r = __shfl_down_sync(0xffffffffu, v.x, 1);

    if (lane == 0) {
        // x-reflect at col 0: left neighbor of col 0 is col 1 == v.y (no load)
        l = (x4 == 0) ? v.y : __ldg(rowp + x4 - 1);
    }
    if (lane == 31) {
        // x-reflect at col 511: right neighbor is col 510 == v.z (no load)
        r = (x4 + 4 == IMG_W) ? v.z : __ldg(rowp + x4 + 4);
    }

    Sorted s;
    sort3(l,   v.x, v.y, s.lo[0], s.mi[0], s.hi[0]);
    sort3(v.x, v.y, v.z, s.lo[1], s.mi[1], s.hi[1]);
    sort3(v.y, v.z, v.w, s.lo[2], s.mi[2], s.hi[2]);
    sort3(v.z, v.w, r,   s.lo[3], s.mi[3], s.hi[3]);
    return s;
}

__global__ __launch_bounds__(NTHREADS, 11)
void MedianFilter2D_68745246540291_kernel(const float* __restrict__ in,
                                          float* __restrict__ out) {
    const int tid    = threadIdx.x;          // 0..127
    const int lane   = tid & 31;
    const int x4     = tid << 2;
    const int stripe = blockIdx.x & 31;      // 32 stripes of 16 rows
    const int plane  = blockIdx.x >> 5;      // 48 planes (B*C)

    const float* img  = in  + (size_t)plane * IMG_H * IMG_W;
    float*       oimg = out + (size_t)plane * IMG_H * IMG_W;

    const int y0 = stripe * ROWS;

    // y-reflection can only occur on the very first and very last loaded rows.
    const int y_top = (y0 == 0) ? 1 : (y0 - 1);

    Sorted S[3];
    S[0] = hsort_row(img + (size_t)y_top * IMG_W, tid, lane, x4);
    S[1] = hsort_row(img + (size_t)y0 * IMG_W,    tid, lane, x4);

    float4* orow = reinterpret_cast<float4*>(oimg + (size_t)y0 * IMG_W) + tid;

#pragma unroll
    for (int i = 0; i < ROWS; i++) {
        int y = y0 + i + 1;
        if (i == ROWS - 1) {
            // only the final load can fall off the bottom (stripe 31)
            y = (y == IMG_H) ? (IMG_H - 2) : y;
        }
        S[(i + 2) % 3] = hsort_row(img + (size_t)y * IMG_W, tid, lane, x4);

        const Sorted& A = S[i % 3];
        const Sorted& B = S[(i + 1) % 3];
        const Sorted& C = S[(i + 2) % 3];

        float4 o;
        o.x = med3(max3(A.lo[0], B.lo[0], C.lo[0]),
                   med3(A.mi[0], B.mi[0], C.mi[0]),
                   min3(A.hi[0], B.hi[0], C.hi[0]));
        o.y = med3(max3(A.lo[1], B.lo[1], C.lo[1]),
                   med3(A.mi[1], B.mi[1], C.mi[1]),
                   min3(A.hi[1], B.hi[1], C.hi[1]));
        o.z = med3(max3(A.lo[2], B.lo[2], C.lo[2]),
                   med3(A.mi[2], B.mi[2], C.mi[2]),
                   min3(A.hi[2], B.hi[2], C.hi[2]));
        o.w = med3(max3(A.lo[3], B.lo[3], C.lo[3]),
                   med3(A.mi[3], B.mi[3], C.mi[3]),
                   min3(A.hi[3], B.hi[3], C.hi[3]));

        *orow = o;
        orow += IMG_W / 4;
    }
}

extern "C" void kernel_launch(void* const* d_in, const int* in_sizes, int n_in,
                              void* d_out, int out_size) {
    const float* in  = (const float*)d_in[0];
    float*       out = (float*)d_out;

    // 16 * 3 = 48 planes, 32 row-stripes per plane = 1536 blocks
    // (fits in a single wave at 11 blocks/SM on 148 SMs)
    dim3 grid(48 * 32);
    dim3 block(NTHREADS);
    MedianFilter2D_68745246540291_kernel<<<grid, block>>>(in, out);
}